// round 3
// baseline (speedup 1.0000x reference)
#include <cuda_runtime.h>

// ---------------------------------------------------------------------------
// Round 3: constant-memory weights (uniform LDCU port, zero L1 crossbar cost)
// + direct coalesced LDG.128 pixel streaming (no input smem tiles)
// + lean accumulators (one 8ch x 4pair set live at a time; k/att/x parked in
//   a padded smem exchange) -> ~115 regs -> 4 CTAs/SM.
// Prep kernel packs duplicated f32x2 weights into __device__ scratch, then
// cudaMemcpyToSymbolAsync -> __constant__ (graph-capturable, every replay).
// ---------------------------------------------------------------------------

typedef unsigned long long u64;

__device__ __forceinline__ u64 pk2(float lo, float hi) {
    u64 r; asm("mov.b64 %0, {%1, %2};" : "=l"(r) : "f"(lo), "f"(hi)); return r;
}
__device__ __forceinline__ void up2(u64 v, float& lo, float& hi) {
    asm("mov.b64 {%0, %1}, %2;" : "=f"(lo), "=f"(hi) : "l"(v));
}
__device__ __forceinline__ void fma2(u64& d, u64 a, u64 b) {
    asm("fma.rn.f32x2 %0, %1, %2, %0;" : "+l"(d) : "l"(a), "l"(b));
}
__device__ __forceinline__ u64 add2(u64 a, u64 b) {
    u64 r; asm("add.rn.f32x2 %0, %1, %2;" : "=l"(r) : "l"(a), "l"(b)); return r;
}
__device__ __forceinline__ u64 mul2(u64 a, u64 b) {
    u64 r; asm("mul.rn.f32x2 %0, %1, %2;" : "=l"(r) : "l"(a), "l"(b)); return r;
}
__device__ __forceinline__ u64 relu2(u64 a) {
    float lo, hi; up2(a, lo, hi);
    return pk2(fmaxf(lo, 0.0f), fmaxf(hi, 0.0f));
}

struct CW {
    u64 wk[64][32];   // duplicated pairs (w,w), [c][o]
    u64 wv[64][32];
    u64 wq[64][32];
    u64 w1[32][16];   // d1: [in][out]
    u64 w2[16][8];
    u64 w3[8][16];
    u64 kb2[32], vb2[32], qb2[32], b3[16];
    float sc;
};
__constant__ CW cw;
__device__   CW cw_scratch;

__global__ void prep_kernel(const float* __restrict__ kw, const float* __restrict__ vw,
                            const float* __restrict__ qw, const float* __restrict__ kb,
                            const float* __restrict__ vb, const float* __restrict__ qb,
                            const float* __restrict__ d1w, const float* __restrict__ d2w,
                            const float* __restrict__ d3w, const float* __restrict__ d3b,
                            const float* __restrict__ scp)
{
    int t = blockIdx.x * blockDim.x + threadIdx.x;   // 2048 threads
    if (t < 2048) {
        int c = t >> 5, o = t & 31;
        cw_scratch.wk[c][o] = pk2(kw[o * 64 + c], kw[o * 64 + c]);
        cw_scratch.wv[c][o] = pk2(vw[o * 64 + c], vw[o * 64 + c]);
        cw_scratch.wq[c][o] = pk2(qw[o * 64 + c], qw[o * 64 + c]);
    }
    if (t < 512) {
        int in = t >> 4, o = t & 15;
        cw_scratch.w1[in][o] = pk2(d1w[o * 32 + in], d1w[o * 32 + in]);
    }
    if (t < 128) {
        int in = t >> 3, o = t & 7;
        cw_scratch.w2[in][o] = pk2(d2w[o * 16 + in], d2w[o * 16 + in]);
        int in3 = t >> 4, o3 = t & 15;
        cw_scratch.w3[in3][o3] = pk2(d3w[o3 * 8 + in3], d3w[o3 * 8 + in3]);
    }
    if (t < 32) {
        cw_scratch.kb2[t] = pk2(kb[t], kb[t]);
        cw_scratch.vb2[t] = pk2(vb[t], vb[t]);
        cw_scratch.qb2[t] = pk2(qb[t], qb[t]);
    }
    if (t < 16) cw_scratch.b3[t] = pk2(d3b[t], d3b[t]);
    if (t == 0) cw_scratch.sc = scp[0];
}

// Pixel-pair ownership: lane tx, j in 0..3 -> quad q=j>>1, jj=j&1.
// pixels [4tx+128q .. 4tx+3+128q]; pair index pr = 2tx + jj + 64q.
#define PR(tx, j) (2 * (tx) + ((j) & 1) + 64 * ((j) >> 1))

#define PROJ(WARR)                                                         \
    _Pragma("unroll")                                                      \
    for (int i = 0; i < 8; i++)                                            \
        _Pragma("unroll")                                                  \
        for (int j = 0; j < 4; j++) acc[i][j] = 0ull;                      \
    _Pragma("unroll 4")                                                    \
    for (int c = 0; c < 64; c++) {                                         \
        ulonglong2 xA = *(const ulonglong2*)(srcp + ((size_t)c << 16));    \
        ulonglong2 xB = *(const ulonglong2*)(srcp + ((size_t)c << 16) + 128); \
        u64 xd0 = xA.x, xd1 = xA.y, xd2 = xB.x, xd3 = xB.y;                \
        _Pragma("unroll")                                                  \
        for (int i = 0; i < 8; i++) {                                      \
            u64 w = cw.WARR[c][ob + i];                                    \
            fma2(acc[i][0], w, xd0);                                       \
            fma2(acc[i][1], w, xd1);                                       \
            fma2(acc[i][2], w, xd2);                                       \
            fma2(acc[i][3], w, xd3);                                       \
        }                                                                  \
    }

__global__ void __launch_bounds__(128, 4)
att_main(const float* __restrict__ kv, const float* __restrict__ qin,
         float* __restrict__ out)
{
    __shared__ u64 xs[128][33];            // [pair][channel], pad 33

    const int tid = threadIdx.x;
    const int tx  = tid & 31;
    const int ob  = (tid >> 5) * 8;        // this warp's channel base

    const int g0 = blockIdx.x << 8;        // 256 px per block
    const int b  = g0 >> 16;
    const int p0 = g0 & 65535;

    const float* srcp;
    const float* kvp = kv  + ((size_t)b << 22) + p0 + 4 * tx;
    const float* qp  = qin + ((size_t)b << 22) + p0 + 4 * tx;

    u64 acc[8][4];

    // ---- K projection -> (k + kb) parked in xs ----
    srcp = kvp;
    PROJ(wk)
#pragma unroll
    for (int i = 0; i < 8; i++) {
        u64 kb = cw.kb2[ob + i];
#pragma unroll
        for (int j = 0; j < 4; j++) xs[PR(tx, j)][ob + i] = add2(acc[i][j], kb);
    }

    // ---- Q projection; gate -> att parked in xs (overwrite) ----
    srcp = qp;
    PROJ(wq)
    {
        const float sc = cw.sc;
#pragma unroll
        for (int i = 0; i < 8; i++) {
            u64 qb = cw.qb2[ob + i];
#pragma unroll
            for (int j = 0; j < 4; j++) {
                u64 kp = xs[PR(tx, j)][ob + i];
                u64 qv = add2(acc[i][j], qb);
                float k0, k1, q0, q1;
                up2(kp, k0, k1); up2(qv, q0, q1);
                float t0 = k0 * q0 * sc;
                float t1 = k1 * q1 * sc;
                float a0 = __fdividef(1.0f, 1.0f + __expf(-t0));
                float a1 = __fdividef(1.0f, 1.0f + __expf(-t1));
                xs[PR(tx, j)][ob + i] = pk2(a0, a1);
            }
        }
    }

    // ---- V projection; x = att * (v + vb) parked in xs ----
    srcp = kvp;
    PROJ(wv)
#pragma unroll
    for (int i = 0; i < 8; i++) {
        u64 vb = cw.vb2[ob + i];
#pragma unroll
        for (int j = 0; j < 4; j++) {
            u64 att = xs[PR(tx, j)][ob + i];
            xs[PR(tx, j)][ob + i] = mul2(att, add2(acc[i][j], vb));
        }
    }
    __syncthreads();

    // ---- tail MLP: thread owns pair `tid` (pixels 2*tid, 2*tid+1) ----
    u64 x[32];
#pragma unroll
    for (int o = 0; o < 32; o++) x[o] = xs[tid][o];

    u64 h[16];
#pragma unroll
    for (int o = 0; o < 16; o++) h[o] = 0ull;
#pragma unroll 4
    for (int in = 0; in < 32; in++) {
        u64 xi = x[in];
#pragma unroll
        for (int o = 0; o < 16; o++) fma2(h[o], cw.w1[in][o], xi);
    }
#pragma unroll
    for (int o = 0; o < 16; o++) h[o] = relu2(h[o]);

    u64 g[8];
#pragma unroll
    for (int o = 0; o < 8; o++) g[o] = 0ull;
#pragma unroll 4
    for (int in = 0; in < 16; in++) {
        u64 xi = h[in];
#pragma unroll
        for (int o = 0; o < 8; o++) fma2(g[o], cw.w2[in][o], xi);
    }
#pragma unroll
    for (int o = 0; o < 8; o++) g[o] = relu2(g[o]);

    u64 y[16];
#pragma unroll
    for (int o = 0; o < 16; o++) y[o] = cw.b3[o];
#pragma unroll
    for (int in = 0; in < 8; in++) {
        u64 xi = g[in];
#pragma unroll
        for (int o = 0; o < 16; o++) fma2(y[o], cw.w3[in][o], xi);
    }

    float* outp = out + ((size_t)b << 20) + p0 + 2 * tid;
#pragma unroll
    for (int o = 0; o < 16; o++)
        *(u64*)(outp + ((size_t)o << 16)) = y[o];
}

extern "C" void kernel_launch(void* const* d_in, const int* in_sizes, int n_in,
                              void* d_out, int out_size)
{
    const float* kv  = (const float*)d_in[0];
    const float* qin = (const float*)d_in[1];
    const float* kw  = (const float*)d_in[2];
    const float* kb  = (const float*)d_in[3];
    const float* vw  = (const float*)d_in[4];
    const float* vb  = (const float*)d_in[5];
    const float* qw  = (const float*)d_in[6];
    const float* qb  = (const float*)d_in[7];
    const float* sc  = (const float*)d_in[8];
    const float* d1w = (const float*)d_in[9];
    const float* d2w = (const float*)d_in[10];
    const float* d3w = (const float*)d_in[11];
    const float* d3b = (const float*)d_in[12];
    float* out = (float*)d_out;

    prep_kernel<<<8, 256>>>(kw, vw, qw, kb, vb, qb, d1w, d2w, d3w, d3b, sc);

    void* scratch_ptr = nullptr;
    cudaGetSymbolAddress(&scratch_ptr, cw_scratch);
    cudaMemcpyToSymbolAsync(cw, scratch_ptr, sizeof(CW), 0,
                            cudaMemcpyDeviceToDevice, 0);

    const int total_px = 16 * 256 * 256;       // 1048576
    att_main<<<total_px / 256, 128>>>(kv, qin, out);
}